// round 1
// baseline (speedup 1.0000x reference)
#include <cuda_runtime.h>
#include <math.h>

// Problem constants
#define BATCH 8
#define SEQ   2048
#define DIM   768
#define ROWS  (BATCH * SEQ)   // 16384
#define LN_EPS 1e-5f

// Scratch (allocation-free: __device__ globals)
__device__ float g_hn[ROWS * DIM];
__device__ float g_q [ROWS * DIM];
__device__ float g_k [ROWS * DIM];

// ---------------------------------------------------------------------------
// 1) LayerNorm: one block per row, 256 threads, 3 elements/thread
// ---------------------------------------------------------------------------
__global__ void __launch_bounds__(256) ln_kernel(
    const float* __restrict__ h,
    const float* __restrict__ gamma,
    const float* __restrict__ beta)
{
    const int row = blockIdx.x;
    const int tid = threadIdx.x;
    const float* x = h + (size_t)row * DIM;

    float v0 = x[tid];
    float v1 = x[tid + 256];
    float v2 = x[tid + 512];

    float s  = v0 + v1 + v2;
    float sq = v0 * v0 + v1 * v1 + v2 * v2;

    // warp reduce
    #pragma unroll
    for (int o = 16; o > 0; o >>= 1) {
        s  += __shfl_xor_sync(0xFFFFFFFFu, s,  o);
        sq += __shfl_xor_sync(0xFFFFFFFFu, sq, o);
    }
    __shared__ float rs[8], rq[8], stat[2];
    const int warp = tid >> 5, lane = tid & 31;
    if (lane == 0) { rs[warp] = s; rq[warp] = sq; }
    __syncthreads();
    if (tid == 0) {
        float ts = 0.f, tq = 0.f;
        #pragma unroll
        for (int i = 0; i < 8; i++) { ts += rs[i]; tq += rq[i]; }
        float mean = ts * (1.0f / DIM);
        float var  = tq * (1.0f / DIM) - mean * mean;
        stat[0] = mean;
        stat[1] = rsqrtf(var + LN_EPS);
    }
    __syncthreads();
    const float mean = stat[0], rstd = stat[1];

    float* o = g_hn + (size_t)row * DIM;
    o[tid]       = (v0 - mean) * rstd * gamma[tid]       + beta[tid];
    o[tid + 256] = (v1 - mean) * rstd * gamma[tid + 256] + beta[tid + 256];
    o[tid + 512] = (v2 - mean) * rstd * gamma[tid + 512] + beta[tid + 512];
}

// ---------------------------------------------------------------------------
// 2) Projection SGEMM: C[M,768] = A[M,768] * W[768,768] + bias
//    128x128 tile, BK=8, 256 threads, 8x8 per-thread microtile
// ---------------------------------------------------------------------------
__global__ void __launch_bounds__(256) gemm_proj(
    const float* __restrict__ W,
    const float* __restrict__ bias,
    float* __restrict__ C)
{
    __shared__ float As[8][128];
    __shared__ float Bs[8][128];

    const int tid  = threadIdx.x;
    const int row0 = blockIdx.y * 128;
    const int col0 = blockIdx.x * 128;
    const int tx = tid & 15, ty = tid >> 4;

    // A tile loader: thread -> (row = tid/2, 4 cols at (tid&1)*4), transposed store
    const int aRow = tid >> 1;
    const int aCol = (tid & 1) * 4;
    // B tile loader: thread -> (k-row = tid/32, 4 cols at (tid&31)*4)
    const int bRow = tid >> 5;
    const int bCol = (tid & 31) * 4;

    const float* A = g_hn;
    float acc[8][8] = {};

    for (int k0 = 0; k0 < DIM; k0 += 8) {
        float4 av = *(const float4*)&A[(size_t)(row0 + aRow) * DIM + k0 + aCol];
        As[aCol + 0][aRow] = av.x;
        As[aCol + 1][aRow] = av.y;
        As[aCol + 2][aRow] = av.z;
        As[aCol + 3][aRow] = av.w;
        float4 wv = *(const float4*)&W[(size_t)(k0 + bRow) * DIM + col0 + bCol];
        *(float4*)&Bs[bRow][bCol] = wv;
        __syncthreads();

        #pragma unroll
        for (int kk = 0; kk < 8; kk++) {
            float4 a0 = *(const float4*)&As[kk][ty * 8];
            float4 a1 = *(const float4*)&As[kk][ty * 8 + 4];
            float4 b0 = *(const float4*)&Bs[kk][tx * 8];
            float4 b1 = *(const float4*)&Bs[kk][tx * 8 + 4];
            float ar[8] = {a0.x, a0.y, a0.z, a0.w, a1.x, a1.y, a1.z, a1.w};
            float br[8] = {b0.x, b0.y, b0.z, b0.w, b1.x, b1.y, b1.z, b1.w};
            #pragma unroll
            for (int i = 0; i < 8; i++)
                #pragma unroll
                for (int j = 0; j < 8; j++)
                    acc[i][j] = fmaf(ar[i], br[j], acc[i][j]);
        }
        __syncthreads();
    }

    #pragma unroll
    for (int i = 0; i < 8; i++) {
        const int r = row0 + ty * 8 + i;
        #pragma unroll
        for (int j = 0; j < 8; j += 4) {
            const int c = col0 + tx * 8 + j;
            float4 o;
            o.x = acc[i][j + 0] + bias[c + 0];
            o.y = acc[i][j + 1] + bias[c + 1];
            o.z = acc[i][j + 2] + bias[c + 2];
            o.w = acc[i][j + 3] + bias[c + 3];
            *(float4*)&C[(size_t)r * DIM + c] = o;
        }
    }
}

// ---------------------------------------------------------------------------
// 3) Batched scores NT SGEMM: out[b,i,j] = sum_d q[b,i,d] * k[b,j,d]
// ---------------------------------------------------------------------------
__global__ void __launch_bounds__(256) gemm_scores(float* __restrict__ outp)
{
    __shared__ float As[8][128];
    __shared__ float Bs[8][128];

    const int b    = blockIdx.z;
    const int tid  = threadIdx.x;
    const int row0 = blockIdx.y * 128;
    const int col0 = blockIdx.x * 128;
    const int tx = tid & 15, ty = tid >> 4;

    const float* Aq = g_q + (size_t)b * SEQ * DIM;
    const float* Ak = g_k + (size_t)b * SEQ * DIM;

    const int lRow = tid >> 1;
    const int lCol = (tid & 1) * 4;

    float acc[8][8] = {};

    for (int k0 = 0; k0 < DIM; k0 += 8) {
        float4 av = *(const float4*)&Aq[(size_t)(row0 + lRow) * DIM + k0 + lCol];
        As[lCol + 0][lRow] = av.x;
        As[lCol + 1][lRow] = av.y;
        As[lCol + 2][lRow] = av.z;
        As[lCol + 3][lRow] = av.w;
        float4 bv = *(const float4*)&Ak[(size_t)(col0 + lRow) * DIM + k0 + lCol];
        Bs[lCol + 0][lRow] = bv.x;
        Bs[lCol + 1][lRow] = bv.y;
        Bs[lCol + 2][lRow] = bv.z;
        Bs[lCol + 3][lRow] = bv.w;
        __syncthreads();

        #pragma unroll
        for (int kk = 0; kk < 8; kk++) {
            float4 a0 = *(const float4*)&As[kk][ty * 8];
            float4 a1 = *(const float4*)&As[kk][ty * 8 + 4];
            float4 b0 = *(const float4*)&Bs[kk][tx * 8];
            float4 b1 = *(const float4*)&Bs[kk][tx * 8 + 4];
            float ar[8] = {a0.x, a0.y, a0.z, a0.w, a1.x, a1.y, a1.z, a1.w};
            float br[8] = {b0.x, b0.y, b0.z, b0.w, b1.x, b1.y, b1.z, b1.w};
            #pragma unroll
            for (int i = 0; i < 8; i++)
                #pragma unroll
                for (int j = 0; j < 8; j++)
                    acc[i][j] = fmaf(ar[i], br[j], acc[i][j]);
        }
        __syncthreads();
    }

    float* o = outp + (size_t)b * SEQ * SEQ;
    #pragma unroll
    for (int i = 0; i < 8; i++) {
        const int r = row0 + ty * 8 + i;
        #pragma unroll
        for (int j = 0; j < 8; j += 4) {
            const int c = col0 + tx * 8 + j;
            float4 v;
            v.x = acc[i][j + 0];
            v.y = acc[i][j + 1];
            v.z = acc[i][j + 2];
            v.w = acc[i][j + 3];
            *(float4*)&o[(size_t)r * SEQ + c] = v;
        }
    }
}

// ---------------------------------------------------------------------------
// 4) In-place row softmax over 2048 columns: one block (256 thr) per row
// ---------------------------------------------------------------------------
__global__ void __launch_bounds__(256) softmax_kernel(float* __restrict__ data)
{
    const size_t row = blockIdx.x;
    float* p = data + row * (size_t)SEQ;
    const int tid = threadIdx.x;

    float v[8];
    float mx = -INFINITY;
    #pragma unroll
    for (int i = 0; i < 8; i++) {
        v[i] = p[i * 256 + tid];
        mx = fmaxf(mx, v[i]);
    }
    #pragma unroll
    for (int o = 16; o > 0; o >>= 1)
        mx = fmaxf(mx, __shfl_xor_sync(0xFFFFFFFFu, mx, o));

    __shared__ float sm[8], ss[8];
    const int warp = tid >> 5, lane = tid & 31;
    if (lane == 0) sm[warp] = mx;
    __syncthreads();
    float m = sm[0];
    #pragma unroll
    for (int i = 1; i < 8; i++) m = fmaxf(m, sm[i]);

    float s = 0.f;
    #pragma unroll
    for (int i = 0; i < 8; i++) {
        v[i] = expf(v[i] - m);
        s += v[i];
    }
    #pragma unroll
    for (int o = 16; o > 0; o >>= 1)
        s += __shfl_xor_sync(0xFFFFFFFFu, s, o);
    if (lane == 0) ss[warp] = s;
    __syncthreads();
    float tot = 0.f;
    #pragma unroll
    for (int i = 0; i < 8; i++) tot += ss[i];
    const float inv = 1.0f / tot;

    #pragma unroll
    for (int i = 0; i < 8; i++)
        p[i * 256 + tid] = v[i] * inv;
}

// ---------------------------------------------------------------------------
// Launcher
// ---------------------------------------------------------------------------
extern "C" void kernel_launch(void* const* d_in, const int* in_sizes, int n_in,
                              void* d_out, int out_size)
{
    const float* h     = (const float*)d_in[0];
    const float* gamma = (const float*)d_in[1];
    const float* beta  = (const float*)d_in[2];
    const float* wq    = (const float*)d_in[3];
    const float* bq    = (const float*)d_in[4];
    const float* wk    = (const float*)d_in[5];
    const float* bk    = (const float*)d_in[6];
    float* out = (float*)d_out;

    float *qptr = nullptr, *kptr = nullptr;
    cudaGetSymbolAddress((void**)&qptr, g_q);
    cudaGetSymbolAddress((void**)&kptr, g_k);

    // 1) LayerNorm
    ln_kernel<<<ROWS, 256>>>(h, gamma, beta);

    // 2) Q and K projections
    dim3 pg(DIM / 128, ROWS / 128);
    gemm_proj<<<pg, 256>>>(wq, bq, qptr);
    gemm_proj<<<pg, 256>>>(wk, bk, kptr);

    // 3) Scores
    dim3 sg(SEQ / 128, SEQ / 128, BATCH);
    gemm_scores<<<sg, 256>>>(out);

    // 4) Softmax in place
    softmax_kernel<<<ROWS, 256>>>(out);
}

// round 3
// speedup vs baseline: 2.1005x; 2.1005x over previous
#include <cuda_runtime.h>
#include <cuda_fp16.h>
#include <math.h>
#include <cstdint>

#define BATCH 8
#define SEQ   2048
#define DIM   768
#define ROWS  (BATCH * SEQ)   // 16384
#define LN_EPS 1e-5f

// ---------------------------------------------------------------------------
// Scratch (allocation-free: __device__ globals)
// ---------------------------------------------------------------------------
__device__ __half g_hn_hi[ROWS * DIM];
__device__ __half g_hn_lo[ROWS * DIM];
__device__ __half g_wqt_hi[DIM * DIM];
__device__ __half g_wqt_lo[DIM * DIM];
__device__ __half g_wkt_hi[DIM * DIM];
__device__ __half g_wkt_lo[DIM * DIM];
__device__ __half g_q_hi[ROWS * DIM];
__device__ __half g_q_lo[ROWS * DIM];
__device__ __half g_k_hi[ROWS * DIM];
__device__ __half g_k_lo[ROWS * DIM];

// ---------------------------------------------------------------------------
// PTX helpers (baseline sm_80+ features only — no tcgen05 on this toolchain)
// ---------------------------------------------------------------------------
__device__ __forceinline__ uint32_t cvta_s(const void* p) {
    uint32_t a;
    asm("{ .reg .u64 t; cvta.to.shared.u64 t, %1; cvt.u32.u64 %0, t; }"
        : "=r"(a) : "l"(p));
    return a;
}
__device__ __forceinline__ void cp16(uint32_t dst, const void* src) {
    asm volatile("cp.async.cg.shared.global [%0], [%1], 16;" :: "r"(dst), "l"(src));
}
#define CP_COMMIT() asm volatile("cp.async.commit_group;" ::: "memory")
#define CP_WAIT1()  asm volatile("cp.async.wait_group 1;" ::: "memory")

__device__ __forceinline__ void ldm4(uint32_t& r0, uint32_t& r1, uint32_t& r2,
                                     uint32_t& r3, uint32_t addr) {
    asm volatile("ldmatrix.sync.aligned.m8n8.x4.shared.b16 {%0,%1,%2,%3}, [%4];"
                 : "=r"(r0), "=r"(r1), "=r"(r2), "=r"(r3) : "r"(addr));
}
__device__ __forceinline__ void mma16816(float* d, const uint32_t* a,
                                         uint32_t b0, uint32_t b1) {
    asm volatile(
        "mma.sync.aligned.m16n8k16.row.col.f32.f16.f16.f32 "
        "{%0,%1,%2,%3}, {%4,%5,%6,%7}, {%8,%9}, {%0,%1,%2,%3};"
        : "+f"(d[0]), "+f"(d[1]), "+f"(d[2]), "+f"(d[3])
        : "r"(a[0]), "r"(a[1]), "r"(a[2]), "r"(a[3]), "r"(b0), "r"(b1));
}

// ---------------------------------------------------------------------------
// 1) LayerNorm + fp16 hi/lo split
// ---------------------------------------------------------------------------
__global__ void __launch_bounds__(256) ln_split_kernel(
    const float* __restrict__ h,
    const float* __restrict__ gamma,
    const float* __restrict__ beta)
{
    const int row = blockIdx.x;
    const int tid = threadIdx.x;
    const float* x = h + (size_t)row * DIM;

    float v0 = x[tid], v1 = x[tid + 256], v2 = x[tid + 512];
    float s  = v0 + v1 + v2;
    float sq = v0 * v0 + v1 * v1 + v2 * v2;
    #pragma unroll
    for (int o = 16; o > 0; o >>= 1) {
        s  += __shfl_xor_sync(0xFFFFFFFFu, s,  o);
        sq += __shfl_xor_sync(0xFFFFFFFFu, sq, o);
    }
    __shared__ float rs[8], rq[8], stat[2];
    const int warp = tid >> 5, lane = tid & 31;
    if (lane == 0) { rs[warp] = s; rq[warp] = sq; }
    __syncthreads();
    if (tid == 0) {
        float ts = 0.f, tq = 0.f;
        #pragma unroll
        for (int i = 0; i < 8; i++) { ts += rs[i]; tq += rq[i]; }
        float mean = ts * (1.0f / DIM);
        float var  = tq * (1.0f / DIM) - mean * mean;
        stat[0] = mean;
        stat[1] = rsqrtf(var + LN_EPS);
    }
    __syncthreads();
    const float mean = stat[0], rstd = stat[1];

    size_t base = (size_t)row * DIM;
    #pragma unroll
    for (int i = 0; i < 3; i++) {
        int c = tid + i * 256;
        float v = (i == 0 ? v0 : (i == 1 ? v1 : v2));
        float y = (v - mean) * rstd * gamma[c] + beta[c];
        __half hi = __float2half_rn(y);
        __half lo = __float2half_rn(y - __half2float(hi));
        g_hn_hi[base + c] = hi;
        g_hn_lo[base + c] = lo;
    }
}

// ---------------------------------------------------------------------------
// 2) Weight transpose + split: Wt[e][d] = W[d][e] (hi/lo fp16)
// ---------------------------------------------------------------------------
__global__ void __launch_bounds__(256) wprep_kernel(
    const float* __restrict__ wq, const float* __restrict__ wk)
{
    __shared__ float t[32][33];
    const float* W = blockIdx.z ? wk : wq;
    __half* Whi = blockIdx.z ? g_wkt_hi : g_wqt_hi;
    __half* Wlo = blockIdx.z ? g_wkt_lo : g_wqt_lo;
    const int x0 = blockIdx.x * 32, y0 = blockIdx.y * 32;
    const int tx = threadIdx.x, ty = threadIdx.y;

    for (int j = ty; j < 32; j += 8)
        t[j][tx] = W[(size_t)(y0 + j) * DIM + x0 + tx];
    __syncthreads();
    for (int j = ty; j < 32; j += 8) {
        float v = t[tx][j];                 // = W[y0+tx][x0+j]
        __half hi = __float2half_rn(v);
        __half lo = __float2half_rn(v - __half2float(hi));
        size_t o = (size_t)(x0 + j) * DIM + y0 + tx;
        Whi[o] = hi;
        Wlo[o] = lo;
    }
}

// ---------------------------------------------------------------------------
// 3) mma.sync fp16-split NT GEMM: C[128,128] per CTA, K = 3*768 virtual
//    (hi*hi, hi*lo, lo*hi).  8 warps in 2x4; warp tile 64x32.
//    mode 0: proj (bias add, write fp16 hi/lo)   mode 1: scores (fp32 out)
// ---------------------------------------------------------------------------
#define PITCH_B   80               // bytes per smem row (32 halfs + 16B skew)
#define OP_BYTES  (128 * PITCH_B)  // 10240 per operand tile
#define STAGE_BYTES (2 * OP_BYTES) // 20480
#define NSTAGE 3
#define GEMM_SMEM (NSTAGE * STAGE_BYTES)   // 61440
#define CHUNK_K 32
#define SEG_CHUNKS (DIM / CHUNK_K)   // 24
#define NCHUNK (3 * SEG_CHUNKS)      // 72

__global__ void __launch_bounds__(256, 2) gemm_f16(
    const __half* __restrict__ Ahi, const __half* __restrict__ Alo,
    const __half* __restrict__ Bhi, const __half* __restrict__ Blo,
    const float* __restrict__ bias,
    float* __restrict__ outF, __half* __restrict__ outHi, __half* __restrict__ outLo,
    int mode)
{
    extern __shared__ __align__(16) char smem[];
    const uint32_t sbase = cvta_s(smem);
    const int tid  = threadIdx.x;
    const int wid  = tid >> 5, lane = tid & 31;
    const int wm   = wid >> 2;          // 0..1  (m block of 64)
    const int wn   = wid & 3;           // 0..3  (n block of 32)

    const int arow0 = blockIdx.z * SEQ + blockIdx.y * 128;
    const int brow0 = blockIdx.z * SEQ + blockIdx.x * 128;  // proj: z==0

    float acc[4][4][4] = {};            // [mi][nj][4]

    // ---- loader: one chunk = A(128x32) + B(128x32) halfs into stage ----
    auto load_chunk = [&](int c) {
        if (c >= NCHUNK) return;
        const int seg  = c / SEG_CHUNKS;
        const int koff = (c - seg * SEG_CHUNKS) * CHUNK_K;
        const __half* As = (seg < 2)  ? Ahi : Alo;
        const __half* Bs = (seg == 1) ? Blo : Bhi;
        const uint32_t st = sbase + (uint32_t)(c % NSTAGE) * STAGE_BYTES;
        #pragma unroll
        for (int i = 0; i < 2; i++) {
            int idx = i * 256 + tid;          // 0..511
            int row = idx >> 2;               // 0..127
            int cg  = idx & 3;                // 16B group
            uint32_t off = (uint32_t)(row * PITCH_B + cg * 16);
            cp16(st + off,
                 As + (size_t)(arow0 + row) * DIM + koff + cg * 8);
            cp16(st + OP_BYTES + off,
                 Bs + (size_t)(brow0 + row) * DIM + koff + cg * 8);
        }
    };

    // ---- compute one chunk (two k16 steps) ----
    auto compute_chunk = [&](int c) {
        const uint32_t st = sbase + (uint32_t)(c % NSTAGE) * STAGE_BYTES;
        const int r16 = lane & 15;
        const int cg  = lane >> 4;           // 0/1 -> k halves
        #pragma unroll
        for (int ks = 0; ks < 2; ks++) {
            uint32_t a[4][4];
            #pragma unroll
            for (int mi = 0; mi < 4; mi++) {
                int row = wm * 64 + mi * 16 + r16;
                uint32_t ad = st + (uint32_t)(row * PITCH_B + ks * 32 + cg * 16);
                ldm4(a[mi][0], a[mi][1], a[mi][2], a[mi][3], ad);
            }
            uint32_t b[4][2];
            #pragma unroll
            for (int nj2 = 0; nj2 < 2; nj2++) {
                int row = wn * 32 + nj2 * 16 + r16;
                uint32_t bd = st + OP_BYTES
                            + (uint32_t)(row * PITCH_B + ks * 32 + cg * 16);
                uint32_t t0, t1, t2, t3;
                ldm4(t0, t1, t2, t3, bd);
                b[nj2 * 2 + 0][0] = t0; b[nj2 * 2 + 0][1] = t2;
                b[nj2 * 2 + 1][0] = t1; b[nj2 * 2 + 1][1] = t3;
            }
            #pragma unroll
            for (int mi = 0; mi < 4; mi++)
                #pragma unroll
                for (int nj = 0; nj < 4; nj++)
                    mma16816(acc[mi][nj], a[mi], b[nj][0], b[nj][1]);
        }
    };

    // ---- pipeline ----
    load_chunk(0); CP_COMMIT();
    load_chunk(1); CP_COMMIT();
    for (int c = 0; c < NCHUNK; c++) {
        CP_WAIT1();                 // chunk c resident
        __syncthreads();
        load_chunk(c + 2); CP_COMMIT();
        compute_chunk(c);
        __syncthreads();            // stage reuse guard
    }

    // ---- epilogue ----
    const int rbase = arow0 + wm * 64 + (lane >> 2);
    const int cbase = blockIdx.x * 128 + wn * 32 + (lane & 3) * 2;
    #pragma unroll
    for (int mi = 0; mi < 4; mi++) {
        #pragma unroll
        for (int half_m = 0; half_m < 2; half_m++) {
            const int r = rbase + mi * 16 + half_m * 8;
            #pragma unroll
            for (int nj = 0; nj < 4; nj++) {
                const int cc = cbase + nj * 8;
                float v0 = acc[mi][nj][half_m * 2 + 0];
                float v1 = acc[mi][nj][half_m * 2 + 1];
                if (mode == 0) {
                    v0 += bias[cc];
                    v1 += bias[cc + 1];
                    __half h0 = __float2half_rn(v0);
                    __half h1 = __float2half_rn(v1);
                    __half l0 = __float2half_rn(v0 - __half2float(h0));
                    __half l1 = __float2half_rn(v1 - __half2float(h1));
                    size_t o = (size_t)r * DIM + cc;
                    *(__half2*)&outHi[o] = __halves2half2(h0, h1);
                    *(__half2*)&outLo[o] = __halves2half2(l0, l1);
                } else {
                    size_t o = (size_t)r * SEQ + cc;
                    float2 v; v.x = v0; v.y = v1;
                    *(float2*)&outF[o] = v;
                }
            }
        }
    }
}

// ---------------------------------------------------------------------------
// 4) Row softmax over 2048 columns
// ---------------------------------------------------------------------------
__global__ void __launch_bounds__(256) softmax_kernel(float* __restrict__ data)
{
    const size_t row = blockIdx.x;
    float* p = data + row * (size_t)SEQ;
    const int tid = threadIdx.x;

    float v[8];
    float mx = -INFINITY;
    #pragma unroll
    for (int i = 0; i < 8; i++) {
        v[i] = p[i * 256 + tid];
        mx = fmaxf(mx, v[i]);
    }
    #pragma unroll
    for (int o = 16; o > 0; o >>= 1)
        mx = fmaxf(mx, __shfl_xor_sync(0xFFFFFFFFu, mx, o));

    __shared__ float sm[8], ss[8];
    const int warp = tid >> 5, lane = tid & 31;
    if (lane == 0) sm[warp] = mx;
    __syncthreads();
    float m = sm[0];
    #pragma unroll
    for (int i = 1; i < 8; i++) m = fmaxf(m, sm[i]);

    float s = 0.f;
    #pragma unroll
    for (int i = 0; i < 8; i++) { v[i] = expf(v[i] - m); s += v[i]; }
    #pragma unroll
    for (int o = 16; o > 0; o >>= 1)
        s += __shfl_xor_sync(0xFFFFFFFFu, s, o);
    if (lane == 0) ss[warp] = s;
    __syncthreads();
    float tot = 0.f;
    #pragma unroll
    for (int i = 0; i < 8; i++) tot += ss[i];
    const float inv = 1.0f / tot;

    #pragma unroll
    for (int i = 0; i < 8; i++)
        p[i * 256 + tid] = v[i] * inv;
}

// ---------------------------------------------------------------------------
// Launcher
// ---------------------------------------------------------------------------
extern "C" void kernel_launch(void* const* d_in, const int* in_sizes, int n_in,
                              void* d_out, int out_size)
{
    const float* h     = (const float*)d_in[0];
    const float* gamma = (const float*)d_in[1];
    const float* beta  = (const float*)d_in[2];
    const float* wq    = (const float*)d_in[3];
    const float* bq    = (const float*)d_in[4];
    const float* wk    = (const float*)d_in[5];
    const float* bk    = (const float*)d_in[6];
    float* out = (float*)d_out;

    cudaFuncSetAttribute(gemm_f16, cudaFuncAttributeMaxDynamicSharedMemorySize,
                         GEMM_SMEM);

    __half *hn_hi, *hn_lo, *wqt_hi, *wqt_lo, *wkt_hi, *wkt_lo, *q_hi, *q_lo, *k_hi, *k_lo;
    cudaGetSymbolAddress((void**)&hn_hi,  g_hn_hi);
    cudaGetSymbolAddress((void**)&hn_lo,  g_hn_lo);
    cudaGetSymbolAddress((void**)&wqt_hi, g_wqt_hi);
    cudaGetSymbolAddress((void**)&wqt_lo, g_wqt_lo);
    cudaGetSymbolAddress((void**)&wkt_hi, g_wkt_hi);
    cudaGetSymbolAddress((void**)&wkt_lo, g_wkt_lo);
    cudaGetSymbolAddress((void**)&q_hi,   g_q_hi);
    cudaGetSymbolAddress((void**)&q_lo,   g_q_lo);
    cudaGetSymbolAddress((void**)&k_hi,   g_k_hi);
    cudaGetSymbolAddress((void**)&k_lo,   g_k_lo);

    // 1) LayerNorm + split
    ln_split_kernel<<<ROWS, 256>>>(h, gamma, beta);

    // 2) Weight transpose + split
    wprep_kernel<<<dim3(24, 24, 2), dim3(32, 8)>>>(wq, wk);

    // 3) Projections: q = hn @ wqT + bq ; k = hn @ wkT + bk
    dim3 pg(DIM / 128, ROWS / 128, 1);
    gemm_f16<<<pg, 256, GEMM_SMEM>>>(hn_hi, hn_lo, wqt_hi, wqt_lo, bq,
                                     nullptr, q_hi, q_lo, 0);
    gemm_f16<<<pg, 256, GEMM_SMEM>>>(hn_hi, hn_lo, wkt_hi, wkt_lo, bk,
                                     nullptr, k_hi, k_lo, 0);

    // 4) Scores
    dim3 sg(SEQ / 128, SEQ / 128, BATCH);
    gemm_f16<<<sg, 256, GEMM_SMEM>>>(q_hi, q_lo, k_hi, k_lo, nullptr,
                                     out, nullptr, nullptr, 1);

    // 5) Softmax in place
    softmax_kernel<<<ROWS, 256>>>(out);
}

// round 4
// speedup vs baseline: 2.2433x; 1.0680x over previous
#include <cuda_runtime.h>
#include <cuda_fp16.h>
#include <math.h>
#include <cstdint>

#define BATCH 8
#define SEQ   2048
#define DIM   768
#define ROWS  (BATCH * SEQ)   // 16384
#define LN_EPS 1e-5f

// ---------------------------------------------------------------------------
// Scratch (allocation-free: __device__ globals)
// ---------------------------------------------------------------------------
__device__ __half g_hn_hi[ROWS * DIM];
__device__ __half g_hn_lo[ROWS * DIM];
__device__ __half g_wqt_hi[DIM * DIM];
__device__ __half g_wqt_lo[DIM * DIM];
__device__ __half g_wkt_hi[DIM * DIM];
__device__ __half g_wkt_lo[DIM * DIM];
__device__ __half g_q_hi[ROWS * DIM];
__device__ __half g_q_lo[ROWS * DIM];
__device__ __half g_k_hi[ROWS * DIM];
__device__ __half g_k_lo[ROWS * DIM];

// ---------------------------------------------------------------------------
// PTX helpers (baseline sm_80+ features only)
// ---------------------------------------------------------------------------
__device__ __forceinline__ uint32_t cvta_s(const void* p) {
    uint32_t a;
    asm("{ .reg .u64 t; cvta.to.shared.u64 t, %1; cvt.u32.u64 %0, t; }"
        : "=r"(a) : "l"(p));
    return a;
}
__device__ __forceinline__ void cp16(uint32_t dst, const void* src) {
    asm volatile("cp.async.cg.shared.global [%0], [%1], 16;" :: "r"(dst), "l"(src));
}
#define CP_COMMIT() asm volatile("cp.async.commit_group;" ::: "memory")
#define CP_WAIT2()  asm volatile("cp.async.wait_group 2;" ::: "memory")

__device__ __forceinline__ void ldm4(uint32_t& r0, uint32_t& r1, uint32_t& r2,
                                     uint32_t& r3, uint32_t addr) {
    asm volatile("ldmatrix.sync.aligned.m8n8.x4.shared.b16 {%0,%1,%2,%3}, [%4];"
                 : "=r"(r0), "=r"(r1), "=r"(r2), "=r"(r3) : "r"(addr));
}
__device__ __forceinline__ void mma16816(float* d, const uint32_t* a,
                                         uint32_t b0, uint32_t b1) {
    asm volatile(
        "mma.sync.aligned.m16n8k16.row.col.f32.f16.f16.f32 "
        "{%0,%1,%2,%3}, {%4,%5,%6,%7}, {%8,%9}, {%0,%1,%2,%3};"
        : "+f"(d[0]), "+f"(d[1]), "+f"(d[2]), "+f"(d[3])
        : "r"(a[0]), "r"(a[1]), "r"(a[2]), "r"(a[3]), "r"(b0), "r"(b1));
}

// ---------------------------------------------------------------------------
// Tiling constants
// ---------------------------------------------------------------------------
#define PITCH_B   80               // bytes per smem row (32 halfs + 16B skew)
#define OP_BYTES  (128 * PITCH_B)  // 10240 per operand tile
#define STAGE_BYTES (2 * OP_BYTES) // 20480
#define NSTAGE 4
#define GEMM_SMEM (NSTAGE * STAGE_BYTES)   // 81920
#define CHUNK_K 32
#define SEG_CHUNKS (DIM / CHUNK_K)   // 24
#define NCHUNK (3 * SEG_CHUNKS)      // 72

// load one chunk: A(128x32) + B(128x32) halfs into a stage
__device__ __forceinline__ void load_chunk_g(
    int c, uint32_t sbase, int tid,
    const __half* __restrict__ Ahi, const __half* __restrict__ Alo,
    const __half* __restrict__ Bhi, const __half* __restrict__ Blo,
    int arow0, int brow0)
{
    if (c >= NCHUNK) return;
    const int seg  = c / SEG_CHUNKS;
    const int koff = (c - seg * SEG_CHUNKS) * CHUNK_K;
    const __half* As = (seg < 2)  ? Ahi : Alo;
    const __half* Bs = (seg == 1) ? Blo : Bhi;
    const uint32_t st = sbase + (uint32_t)(c % NSTAGE) * STAGE_BYTES;
    #pragma unroll
    for (int i = 0; i < 2; i++) {
        int idx = i * 256 + tid;          // 0..511
        int row = idx >> 2;               // 0..127
        int cg  = idx & 3;                // 16B group
        uint32_t off = (uint32_t)(row * PITCH_B + cg * 16);
        cp16(st + off,            As + (size_t)(arow0 + row) * DIM + koff + cg * 8);
        cp16(st + OP_BYTES + off, Bs + (size_t)(brow0 + row) * DIM + koff + cg * 8);
    }
}

// compute one chunk (two k16 steps); warp tile 64x32, warps in 2x4
__device__ __forceinline__ void compute_chunk_g(
    int c, uint32_t sbase, int lane, int wm, int wn, float acc[4][4][4])
{
    const uint32_t st = sbase + (uint32_t)(c % NSTAGE) * STAGE_BYTES;
    const int r16 = lane & 15;
    const int cg  = lane >> 4;
    #pragma unroll
    for (int ks = 0; ks < 2; ks++) {
        uint32_t a[4][4];
        #pragma unroll
        for (int mi = 0; mi < 4; mi++) {
            int row = wm * 64 + mi * 16 + r16;
            uint32_t ad = st + (uint32_t)(row * PITCH_B + ks * 32 + cg * 16);
            ldm4(a[mi][0], a[mi][1], a[mi][2], a[mi][3], ad);
        }
        uint32_t b[4][2];
        #pragma unroll
        for (int nj2 = 0; nj2 < 2; nj2++) {
            int row = wn * 32 + nj2 * 16 + r16;
            uint32_t bd = st + OP_BYTES
                        + (uint32_t)(row * PITCH_B + ks * 32 + cg * 16);
            uint32_t t0, t1, t2, t3;
            ldm4(t0, t1, t2, t3, bd);
            b[nj2 * 2 + 0][0] = t0; b[nj2 * 2 + 0][1] = t2;
            b[nj2 * 2 + 1][0] = t1; b[nj2 * 2 + 1][1] = t3;
        }
        #pragma unroll
        for (int mi = 0; mi < 4; mi++)
            #pragma unroll
            for (int nj = 0; nj < 4; nj++)
                mma16816(acc[mi][nj], a[mi], b[nj][0], b[nj][1]);
    }
}

// ---------------------------------------------------------------------------
// 1) LayerNorm + fp16 hi/lo split
// ---------------------------------------------------------------------------
__global__ void __launch_bounds__(256) ln_split_kernel(
    const float* __restrict__ h,
    const float* __restrict__ gamma,
    const float* __restrict__ beta)
{
    const int row = blockIdx.x;
    const int tid = threadIdx.x;
    const float* x = h + (size_t)row * DIM;

    float v0 = x[tid], v1 = x[tid + 256], v2 = x[tid + 512];
    float s  = v0 + v1 + v2;
    float sq = v0 * v0 + v1 * v1 + v2 * v2;
    #pragma unroll
    for (int o = 16; o > 0; o >>= 1) {
        s  += __shfl_xor_sync(0xFFFFFFFFu, s,  o);
        sq += __shfl_xor_sync(0xFFFFFFFFu, sq, o);
    }
    __shared__ float rs[8], rq[8], stat[2];
    const int warp = tid >> 5, lane = tid & 31;
    if (lane == 0) { rs[warp] = s; rq[warp] = sq; }
    __syncthreads();
    if (tid == 0) {
        float ts = 0.f, tq = 0.f;
        #pragma unroll
        for (int i = 0; i < 8; i++) { ts += rs[i]; tq += rq[i]; }
        float mean = ts * (1.0f / DIM);
        float var  = tq * (1.0f / DIM) - mean * mean;
        stat[0] = mean;
        stat[1] = rsqrtf(var + LN_EPS);
    }
    __syncthreads();
    const float mean = stat[0], rstd = stat[1];

    size_t base = (size_t)row * DIM;
    #pragma unroll
    for (int i = 0; i < 3; i++) {
        int c = tid + i * 256;
        float v = (i == 0 ? v0 : (i == 1 ? v1 : v2));
        float y = (v - mean) * rstd * gamma[c] + beta[c];
        __half hi = __float2half_rn(y);
        __half lo = __float2half_rn(y - __half2float(hi));
        g_hn_hi[base + c] = hi;
        g_hn_lo[base + c] = lo;
    }
}

// ---------------------------------------------------------------------------
// 2) Weight transpose + split: Wt[e][d] = W[d][e] (hi/lo fp16)
// ---------------------------------------------------------------------------
__global__ void __launch_bounds__(256) wprep_kernel(
    const float* __restrict__ wq, const float* __restrict__ wk)
{
    __shared__ float t[32][33];
    const float* W = blockIdx.z ? wk : wq;
    __half* Whi = blockIdx.z ? g_wkt_hi : g_wqt_hi;
    __half* Wlo = blockIdx.z ? g_wkt_lo : g_wqt_lo;
    const int x0 = blockIdx.x * 32, y0 = blockIdx.y * 32;
    const int tx = threadIdx.x, ty = threadIdx.y;

    for (int j = ty; j < 32; j += 8)
        t[j][tx] = W[(size_t)(y0 + j) * DIM + x0 + tx];
    __syncthreads();
    for (int j = ty; j < 32; j += 8) {
        float v = t[tx][j];
        __half hi = __float2half_rn(v);
        __half lo = __float2half_rn(v - __half2float(hi));
        size_t o = (size_t)(x0 + j) * DIM + y0 + tx;
        Whi[o] = hi;
        Wlo[o] = lo;
    }
}

// ---------------------------------------------------------------------------
// 3a) Merged Q+K projection GEMM (mode proj): grid (12, 128)
//     bx<6: q = hn @ wqT + bq ; bx>=6: k = hn @ wkT + bk
// ---------------------------------------------------------------------------
__global__ void __launch_bounds__(256, 2) gemm_proj(const float* __restrict__ bq,
                                                    const float* __restrict__ bk)
{
    extern __shared__ __align__(16) char smem[];
    const uint32_t sbase = cvta_s(smem);
    const int tid = threadIdx.x;
    const int wid = tid >> 5, lane = tid & 31;
    const int wm = wid >> 2, wn = wid & 3;

    const bool isK  = blockIdx.x >= 6;
    const int  nb   = isK ? (int)blockIdx.x - 6 : (int)blockIdx.x;
    const int arow0 = blockIdx.y * 128;
    const int brow0 = nb * 128;

    const __half* Bhi = isK ? g_wkt_hi : g_wqt_hi;
    const __half* Blo = isK ? g_wkt_lo : g_wqt_lo;
    const float*  bias = isK ? bk : bq;
    __half* outHi = isK ? g_k_hi : g_q_hi;
    __half* outLo = isK ? g_k_lo : g_q_lo;

    float acc[4][4][4] = {};

    load_chunk_g(0, sbase, tid, g_hn_hi, g_hn_lo, Bhi, Blo, arow0, brow0); CP_COMMIT();
    load_chunk_g(1, sbase, tid, g_hn_hi, g_hn_lo, Bhi, Blo, arow0, brow0); CP_COMMIT();
    load_chunk_g(2, sbase, tid, g_hn_hi, g_hn_lo, Bhi, Blo, arow0, brow0); CP_COMMIT();

    for (int c = 0; c < NCHUNK; c++) {
        CP_WAIT2();                 // chunk c landed (this thread)
        __syncthreads();            // visible to all; all warps past compute c-1
        load_chunk_g(c + 3, sbase, tid, g_hn_hi, g_hn_lo, Bhi, Blo, arow0, brow0);
        CP_COMMIT();
        compute_chunk_g(c, sbase, lane, wm, wn, acc);
    }

    const int rbase = arow0 + wm * 64 + (lane >> 2);
    const int cbase = nb * 128 + wn * 32 + (lane & 3) * 2;
    #pragma unroll
    for (int mi = 0; mi < 4; mi++) {
        #pragma unroll
        for (int hm = 0; hm < 2; hm++) {
            const int r = rbase + mi * 16 + hm * 8;
            #pragma unroll
            for (int nj = 0; nj < 4; nj++) {
                const int cc = cbase + nj * 8;
                float v0 = acc[mi][nj][hm * 2 + 0] + bias[cc];
                float v1 = acc[mi][nj][hm * 2 + 1] + bias[cc + 1];
                __half h0 = __float2half_rn(v0);
                __half h1 = __float2half_rn(v1);
                __half l0 = __float2half_rn(v0 - __half2float(h0));
                __half l1 = __float2half_rn(v1 - __half2float(h1));
                size_t o = (size_t)r * DIM + cc;
                *(__half2*)&outHi[o] = __halves2half2(h0, h1);
                *(__half2*)&outLo[o] = __halves2half2(l0, l1);
            }
        }
    }
}

// ---------------------------------------------------------------------------
// 3b) Scores GEMM: out[b,i,j] = q[b,i,:] . k[b,j,:]   grid (16, 16, 8)
// ---------------------------------------------------------------------------
__global__ void __launch_bounds__(256, 2) gemm_scores(float* __restrict__ outF)
{
    extern __shared__ __align__(16) char smem[];
    const uint32_t sbase = cvta_s(smem);
    const int tid = threadIdx.x;
    const int wid = tid >> 5, lane = tid & 31;
    const int wm = wid >> 2, wn = wid & 3;

    const int arow0 = blockIdx.z * SEQ + blockIdx.y * 128;
    const int brow0 = blockIdx.z * SEQ + blockIdx.x * 128;

    float acc[4][4][4] = {};

    load_chunk_g(0, sbase, tid, g_q_hi, g_q_lo, g_k_hi, g_k_lo, arow0, brow0); CP_COMMIT();
    load_chunk_g(1, sbase, tid, g_q_hi, g_q_lo, g_k_hi, g_k_lo, arow0, brow0); CP_COMMIT();
    load_chunk_g(2, sbase, tid, g_q_hi, g_q_lo, g_k_hi, g_k_lo, arow0, brow0); CP_COMMIT();

    for (int c = 0; c < NCHUNK; c++) {
        CP_WAIT2();
        __syncthreads();
        load_chunk_g(c + 3, sbase, tid, g_q_hi, g_q_lo, g_k_hi, g_k_lo, arow0, brow0);
        CP_COMMIT();
        compute_chunk_g(c, sbase, lane, wm, wn, acc);
    }

    const int rbase = arow0 + wm * 64 + (lane >> 2);
    const int cbase = blockIdx.x * 128 + wn * 32 + (lane & 3) * 2;
    #pragma unroll
    for (int mi = 0; mi < 4; mi++) {
        #pragma unroll
        for (int hm = 0; hm < 2; hm++) {
            const int r = rbase + mi * 16 + hm * 8;
            #pragma unroll
            for (int nj = 0; nj < 4; nj++) {
                const int cc = cbase + nj * 8;
                float2 v;
                v.x = acc[mi][nj][hm * 2 + 0];
                v.y = acc[mi][nj][hm * 2 + 1];
                *(float2*)&outF[(size_t)r * SEQ + cc] = v;
            }
        }
    }
}

// ---------------------------------------------------------------------------
// 4) Row softmax over 2048 columns
// ---------------------------------------------------------------------------
__global__ void __launch_bounds__(256) softmax_kernel(float* __restrict__ data)
{
    const size_t row = blockIdx.x;
    float* p = data + row * (size_t)SEQ;
    const int tid = threadIdx.x;

    float v[8];
    float mx = -INFINITY;
    #pragma unroll
    for (int i = 0; i < 8; i++) {
        v[i] = p[i * 256 + tid];
        mx = fmaxf(mx, v[i]);
    }
    #pragma unroll
    for (int o = 16; o > 0; o >>= 1)
        mx = fmaxf(mx, __shfl_xor_sync(0xFFFFFFFFu, mx, o));

    __shared__ float sm[8], ss[8];
    const int warp = tid >> 5, lane = tid & 31;
    if (lane == 0) sm[warp] = mx;
    __syncthreads();
    float m = sm[0];
    #pragma unroll
    for (int i = 1; i < 8; i++) m = fmaxf(m, sm[i]);

    float s = 0.f;
    #pragma unroll
    for (int i = 0; i < 8; i++) { v[i] = expf(v[i] - m); s += v[i]; }
    #pragma unroll
    for (int o = 16; o > 0; o >>= 1)
        s += __shfl_xor_sync(0xFFFFFFFFu, s, o);
    if (lane == 0) ss[warp] = s;
    __syncthreads();
    float tot = 0.f;
    #pragma unroll
    for (int i = 0; i < 8; i++) tot += ss[i];
    const float inv = 1.0f / tot;

    #pragma unroll
    for (int i = 0; i < 8; i++)
        p[i * 256 + tid] = v[i] * inv;
}

// ---------------------------------------------------------------------------
// Launcher
// ---------------------------------------------------------------------------
extern "C" void kernel_launch(void* const* d_in, const int* in_sizes, int n_in,
                              void* d_out, int out_size)
{
    const float* h     = (const float*)d_in[0];
    const float* gamma = (const float*)d_in[1];
    const float* beta  = (const float*)d_in[2];
    const float* wq    = (const float*)d_in[3];
    const float* bq    = (const float*)d_in[4];
    const float* wk    = (const float*)d_in[5];
    const float* bk    = (const float*)d_in[6];
    float* out = (float*)d_out;

    cudaFuncSetAttribute(gemm_proj,   cudaFuncAttributeMaxDynamicSharedMemorySize, GEMM_SMEM);
    cudaFuncSetAttribute(gemm_scores, cudaFuncAttributeMaxDynamicSharedMemorySize, GEMM_SMEM);

    // 1) LayerNorm + split
    ln_split_kernel<<<ROWS, 256>>>(h, gamma, beta);

    // 2) Weight transpose + split
    wprep_kernel<<<dim3(24, 24, 2), dim3(32, 8)>>>(wq, wk);

    // 3) Merged Q+K projections
    gemm_proj<<<dim3(12, ROWS / 128), 256, GEMM_SMEM>>>(bq, bk);

    // 4) Scores
    gemm_scores<<<dim3(SEQ / 128, SEQ / 128, BATCH), 256, GEMM_SMEM>>>(out);

    // 5) Softmax in place
    softmax_kernel<<<ROWS, 256>>>(out);
}

// round 6
// speedup vs baseline: 2.6123x; 1.1645x over previous
#include <cuda_runtime.h>
#include <cuda_fp16.h>
#include <math.h>
#include <cstdint>

#define BATCH 8
#define SEQ   2048
#define DIM   768
#define ROWS  (BATCH * SEQ)   // 16384
#define LN_EPS 1e-5f

// ---------------------------------------------------------------------------
// Scratch (allocation-free: __device__ globals)
// ---------------------------------------------------------------------------
__device__ __half g_hn_hi[ROWS * DIM];
__device__ __half g_hn_lo[ROWS * DIM];
__device__ __half g_wqt_hi[DIM * DIM];
__device__ __half g_wqt_lo[DIM * DIM];
__device__ __half g_wkt_hi[DIM * DIM];
__device__ __half g_wkt_lo[DIM * DIM];
__device__ __half g_q_hi[ROWS * DIM];
__device__ __half g_q_lo[ROWS * DIM];
__device__ __half g_k_hi[ROWS * DIM];
__device__ __half g_k_lo[ROWS * DIM];

// ---------------------------------------------------------------------------
// PTX helpers
// ---------------------------------------------------------------------------
__device__ __forceinline__ uint32_t cvta_s(const void* p) {
    uint32_t a;
    asm("{ .reg .u64 t; cvta.to.shared.u64 t, %1; cvt.u32.u64 %0, t; }"
        : "=r"(a) : "l"(p));
    return a;
}
__device__ __forceinline__ void cp16(uint32_t dst, const void* src) {
    asm volatile("cp.async.cg.shared.global [%0], [%1], 16;" :: "r"(dst), "l"(src));
}
#define CP_COMMIT() asm volatile("cp.async.commit_group;" ::: "memory")
#define CP_WAIT0()  asm volatile("cp.async.wait_group 0;" ::: "memory")

__device__ __forceinline__ void ldm4(uint32_t& r0, uint32_t& r1, uint32_t& r2,
                                     uint32_t& r3, uint32_t addr) {
    asm volatile("ldmatrix.sync.aligned.m8n8.x4.shared.b16 {%0,%1,%2,%3}, [%4];"
                 : "=r"(r0), "=r"(r1), "=r"(r2), "=r"(r3) : "r"(addr));
}
__device__ __forceinline__ void mma16816(float* d, const uint32_t* a,
                                         uint32_t b0, uint32_t b1) {
    asm volatile(
        "mma.sync.aligned.m16n8k16.row.col.f32.f16.f16.f32 "
        "{%0,%1,%2,%3}, {%4,%5,%6,%7}, {%8,%9}, {%0,%1,%2,%3};"
        : "+f"(d[0]), "+f"(d[1]), "+f"(d[2]), "+f"(d[3])
        : "r"(a[0]), "r"(a[1]), "r"(a[2]), "r"(a[3]), "r"(b0), "r"(b1));
}

// ---------------------------------------------------------------------------
// Tiling: chunk = K offset of 32; stage holds 4 tiles (Ahi, Alo, Bhi, Blo)
// ---------------------------------------------------------------------------
#define PITCH_B   80               // bytes per smem row (32 halfs + 16B skew)
#define OP_BYTES  (128 * PITCH_B)  // 10240 per operand tile
#define STAGE_BYTES (4 * OP_BYTES) // 40960 per stage (4 tiles)
#define NSTAGE 2
#define GEMM_SMEM (NSTAGE * STAGE_BYTES)   // 81920
#define CHUNK_K 32
#define NCHUNK (DIM / CHUNK_K)     // 24

// load one chunk: 4 tiles of 128x32 halfs each; 8 cp16 per thread
__device__ __forceinline__ void load_chunk4(
    int c, uint32_t sbase, int tid,
    const __half* __restrict__ Ahi, const __half* __restrict__ Alo,
    const __half* __restrict__ Bhi, const __half* __restrict__ Blo,
    int arow0, int brow0)
{
    if (c >= NCHUNK) return;
    const int koff = c * CHUNK_K;
    const uint32_t st = sbase + (uint32_t)(c & 1) * STAGE_BYTES;
    #pragma unroll
    for (int i = 0; i < 2; i++) {
        int idx = i * 256 + tid;          // 0..511
        int row = idx >> 2;               // 0..127
        int cg  = idx & 3;                // 16B group
        uint32_t off = (uint32_t)(row * PITCH_B + cg * 16);
        size_t ga = (size_t)(arow0 + row) * DIM + koff + cg * 8;
        size_t gb = (size_t)(brow0 + row) * DIM + koff + cg * 8;
        cp16(st + 0 * OP_BYTES + off, Ahi + ga);
        cp16(st + 1 * OP_BYTES + off, Alo + ga);
        cp16(st + 2 * OP_BYTES + off, Bhi + gb);
        cp16(st + 3 * OP_BYTES + off, Blo + gb);
    }
}

// compute one chunk: 3 compensated terms; A frags loaded once per ks
__device__ __forceinline__ void compute_chunk4(
    int c, uint32_t sbase, int lane, int wm, int wn, float acc[4][4][4])
{
    const uint32_t st = sbase + (uint32_t)(c & 1) * STAGE_BYTES;
    const int r16 = lane & 15;
    const int cg  = lane >> 4;
    #pragma unroll
    for (int ks = 0; ks < 2; ks++) {
        const uint32_t kso = (uint32_t)(ks * 32 + cg * 16);
        uint32_t ah[4][4], al[4][4];
        #pragma unroll
        for (int mi = 0; mi < 4; mi++) {
            int row = wm * 64 + mi * 16 + r16;
            uint32_t ad = st + (uint32_t)(row * PITCH_B) + kso;
            ldm4(ah[mi][0], ah[mi][1], ah[mi][2], ah[mi][3], ad);
            ldm4(al[mi][0], al[mi][1], al[mi][2], al[mi][3], ad + OP_BYTES);
        }
        uint32_t b[4][2];
        // ---- b_hi terms: ah*bh + al*bh ----
        #pragma unroll
        for (int nj2 = 0; nj2 < 2; nj2++) {
            int row = wn * 32 + nj2 * 16 + r16;
            uint32_t bd = st + 2 * OP_BYTES + (uint32_t)(row * PITCH_B) + kso;
            uint32_t t0, t1, t2, t3;
            ldm4(t0, t1, t2, t3, bd);
            b[nj2 * 2 + 0][0] = t0; b[nj2 * 2 + 0][1] = t2;
            b[nj2 * 2 + 1][0] = t1; b[nj2 * 2 + 1][1] = t3;
        }
        #pragma unroll
        for (int mi = 0; mi < 4; mi++)
            #pragma unroll
            for (int nj = 0; nj < 4; nj++) {
                mma16816(acc[mi][nj], ah[mi], b[nj][0], b[nj][1]);
                mma16816(acc[mi][nj], al[mi], b[nj][0], b[nj][1]);
            }
        // ---- b_lo term: ah*bl ----
        #pragma unroll
        for (int nj2 = 0; nj2 < 2; nj2++) {
            int row = wn * 32 + nj2 * 16 + r16;
            uint32_t bd = st + 3 * OP_BYTES + (uint32_t)(row * PITCH_B) + kso;
            uint32_t t0, t1, t2, t3;
            ldm4(t0, t1, t2, t3, bd);
            b[nj2 * 2 + 0][0] = t0; b[nj2 * 2 + 0][1] = t2;
            b[nj2 * 2 + 1][0] = t1; b[nj2 * 2 + 1][1] = t3;
        }
        #pragma unroll
        for (int mi = 0; mi < 4; mi++)
            #pragma unroll
            for (int nj = 0; nj < 4; nj++)
                mma16816(acc[mi][nj], ah[mi], b[nj][0], b[nj][1]);
    }
}

// ---------------------------------------------------------------------------
// 1) LayerNorm + fp16 hi/lo split
// ---------------------------------------------------------------------------
__global__ void __launch_bounds__(256) ln_split_kernel(
    const float* __restrict__ h,
    const float* __restrict__ gamma,
    const float* __restrict__ beta)
{
    const int row = blockIdx.x;
    const int tid = threadIdx.x;
    const float* x = h + (size_t)row * DIM;

    float v0 = x[tid], v1 = x[tid + 256], v2 = x[tid + 512];
    float s  = v0 + v1 + v2;
    float sq = v0 * v0 + v1 * v1 + v2 * v2;
    #pragma unroll
    for (int o = 16; o > 0; o >>= 1) {
        s  += __shfl_xor_sync(0xFFFFFFFFu, s,  o);
        sq += __shfl_xor_sync(0xFFFFFFFFu, sq, o);
    }
    __shared__ float rs[8], rq[8], stat[2];
    const int warp = tid >> 5, lane = tid & 31;
    if (lane == 0) { rs[warp] = s; rq[warp] = sq; }
    __syncthreads();
    if (tid == 0) {
        float ts = 0.f, tq = 0.f;
        #pragma unroll
        for (int i = 0; i < 8; i++) { ts += rs[i]; tq += rq[i]; }
        float mean = ts * (1.0f / DIM);
        float var  = tq * (1.0f / DIM) - mean * mean;
        stat[0] = mean;
        stat[1] = rsqrtf(var + LN_EPS);
    }
    __syncthreads();
    const float mean = stat[0], rstd = stat[1];

    size_t base = (size_t)row * DIM;
    #pragma unroll
    for (int i = 0; i < 3; i++) {
        int c = tid + i * 256;
        float v = (i == 0 ? v0 : (i == 1 ? v1 : v2));
        float y = (v - mean) * rstd * gamma[c] + beta[c];
        __half hi = __float2half_rn(y);
        __half lo = __float2half_rn(y - __half2float(hi));
        g_hn_hi[base + c] = hi;
        g_hn_lo[base + c] = lo;
    }
}

// ---------------------------------------------------------------------------
// 2) Weight transpose + split
// ---------------------------------------------------------------------------
__global__ void __launch_bounds__(256) wprep_kernel(
    const float* __restrict__ wq, const float* __restrict__ wk)
{
    __shared__ float t[32][33];
    const float* W = blockIdx.z ? wk : wq;
    __half* Whi = blockIdx.z ? g_wkt_hi : g_wqt_hi;
    __half* Wlo = blockIdx.z ? g_wkt_lo : g_wqt_lo;
    const int x0 = blockIdx.x * 32, y0 = blockIdx.y * 32;
    const int tx = threadIdx.x, ty = threadIdx.y;

    for (int j = ty; j < 32; j += 8)
        t[j][tx] = W[(size_t)(y0 + j) * DIM + x0 + tx];
    __syncthreads();
    for (int j = ty; j < 32; j += 8) {
        float v = t[tx][j];
        __half hi = __float2half_rn(v);
        __half lo = __float2half_rn(v - __half2float(hi));
        size_t o = (size_t)(x0 + j) * DIM + y0 + tx;
        Whi[o] = hi;
        Wlo[o] = lo;
    }
}

// ---------------------------------------------------------------------------
// 3a) Merged Q+K projections: grid (12, 128)
// ---------------------------------------------------------------------------
__global__ void __launch_bounds__(256, 2) gemm_proj(const float* __restrict__ bq,
                                                    const float* __restrict__ bk)
{
    extern __shared__ __align__(16) char smem[];
    const uint32_t sbase = cvta_s(smem);
    const int tid = threadIdx.x;
    const int wid = tid >> 5, lane = tid & 31;
    const int wm = wid >> 2, wn = wid & 3;

    const bool isK  = blockIdx.x >= 6;
    const int  nb   = isK ? (int)blockIdx.x - 6 : (int)blockIdx.x;
    const int arow0 = blockIdx.y * 128;
    const int brow0 = nb * 128;

    const __half* Bhi = isK ? g_wkt_hi : g_wqt_hi;
    const __half* Blo = isK ? g_wkt_lo : g_wqt_lo;
    const float*  bias = isK ? bk : bq;
    __half* outHi = isK ? g_k_hi : g_q_hi;
    __half* outLo = isK ? g_k_lo : g_q_lo;

    float acc[4][4][4] = {};

    load_chunk4(0, sbase, tid, g_hn_hi, g_hn_lo, Bhi, Blo, arow0, brow0);
    CP_COMMIT();
    for (int c = 0; c < NCHUNK; c++) {
        CP_WAIT0();
        __syncthreads();
        load_chunk4(c + 1, sbase, tid, g_hn_hi, g_hn_lo, Bhi, Blo, arow0, brow0);
        CP_COMMIT();
        compute_chunk4(c, sbase, lane, wm, wn, acc);
    }

    const int rbase = arow0 + wm * 64 + (lane >> 2);
    const int cbase = nb * 128 + wn * 32 + (lane & 3) * 2;
    #pragma unroll
    for (int mi = 0; mi < 4; mi++) {
        #pragma unroll
        for (int hm = 0; hm < 2; hm++) {
            const int r = rbase + mi * 16 + hm * 8;
            #pragma unroll
            for (int nj = 0; nj < 4; nj++) {
                const int cc = cbase + nj * 8;
                float v0 = acc[mi][nj][hm * 2 + 0] + bias[cc];
                float v1 = acc[mi][nj][hm * 2 + 1] + bias[cc + 1];
                __half h0 = __float2half_rn(v0);
                __half h1 = __float2half_rn(v1);
                __half l0 = __float2half_rn(v0 - __half2float(h0));
                __half l1 = __float2half_rn(v1 - __half2float(h1));
                size_t o = (size_t)r * DIM + cc;
                *(__half2*)&outHi[o] = __halves2half2(h0, h1);
                *(__half2*)&outLo[o] = __halves2half2(l0, l1);
            }
        }
    }
}

// ---------------------------------------------------------------------------
// 3b) Scores GEMM: grid (16, 16, 8)
// ---------------------------------------------------------------------------
__global__ void __launch_bounds__(256, 2) gemm_scores(float* __restrict__ outF)
{
    extern __shared__ __align__(16) char smem[];
    const uint32_t sbase = cvta_s(smem);
    const int tid = threadIdx.x;
    const int wid = tid >> 5, lane = tid & 31;
    const int wm = wid >> 2, wn = wid & 3;

    const int arow0 = blockIdx.z * SEQ + blockIdx.y * 128;
    const int brow0 = blockIdx.z * SEQ + blockIdx.x * 128;

    float acc[4][4][4] = {};

    load_chunk4(0, sbase, tid, g_q_hi, g_q_lo, g_k_hi, g_k_lo, arow0, brow0);
    CP_COMMIT();
    for (int c = 0; c < NCHUNK; c++) {
        CP_WAIT0();
        __syncthreads();
        load_chunk4(c + 1, sbase, tid, g_q_hi, g_q_lo, g_k_hi, g_k_lo, arow0, brow0);
        CP_COMMIT();
        compute_chunk4(c, sbase, lane, wm, wn, acc);
    }

    const int rbase = arow0 + wm * 64 + (lane >> 2);
    const int cbase = blockIdx.x * 128 + wn * 32 + (lane & 3) * 2;
    #pragma unroll
    for (int mi = 0; mi < 4; mi++) {
        #pragma unroll
        for (int hm = 0; hm < 2; hm++) {
            const int r = rbase + mi * 16 + hm * 8;
            #pragma unroll
            for (int nj = 0; nj < 4; nj++) {
                const int cc = cbase + nj * 8;
                float2 v;
                v.x = acc[mi][nj][hm * 2 + 0];
                v.y = acc[mi][nj][hm * 2 + 1];
                *(float2*)&outF[(size_t)r * SEQ + cc] = v;
            }
        }
    }
}

// ---------------------------------------------------------------------------
// 4) Row softmax over 2048 columns
// ---------------------------------------------------------------------------
__global__ void __launch_bounds__(256) softmax_kernel(float* __restrict__ data)
{
    const size_t row = blockIdx.x;
    float* p = data + row * (size_t)SEQ;
    const int tid = threadIdx.x;

    float v[8];
    float mx = -INFINITY;
    #pragma unroll
    for (int i = 0; i < 8; i++) {
        v[i] = p[i * 256 + tid];
        mx = fmaxf(mx, v[i]);
    }
    #pragma unroll
    for (int o = 16; o > 0; o >>= 1)
        mx = fmaxf(mx, __shfl_xor_sync(0xFFFFFFFFu, mx, o));

    __shared__ float sm[8], ss[8];
    const int warp = tid >> 5, lane = tid & 31;
    if (lane == 0) sm[warp] = mx;
    __syncthreads();
    float m = sm[0];
    #pragma unroll
    for (int i = 1; i < 8; i++) m = fmaxf(m, sm[i]);

    float s = 0.f;
    #pragma unroll
    for (int i = 0; i < 8; i++) { v[i] = expf(v[i] - m); s += v[i]; }
    #pragma unroll
    for (int o = 16; o > 0; o >>= 1)
        s += __shfl_xor_sync(0xFFFFFFFFu, s, o);
    if (lane == 0) ss[warp] = s;
    __syncthreads();
    float tot = 0.f;
    #pragma unroll
    for (int i = 0; i < 8; i++) tot += ss[i];
    const float inv = 1.0f / tot;

    #pragma unroll
    for (int i = 0; i < 8; i++)
        p[i * 256 + tid] = v[i] * inv;
}

// ---------------------------------------------------------------------------
// Launcher
// ---------------------------------------------------------------------------
extern "C" void kernel_launch(void* const* d_in, const int* in_sizes, int n_in,
                              void* d_out, int out_size)
{
    const float* h     = (const float*)d_in[0];
    const float* gamma = (const float*)d_in[1];
    const float* beta  = (const float*)d_in[2];
    const float* wq    = (const float*)d_in[3];
    const float* bq    = (const float*)d_in[4];
    const float* wk    = (const float*)d_in[5];
    const float* bk    = (const float*)d_in[6];
    float* out = (float*)d_out;

    cudaFuncSetAttribute(gemm_proj,   cudaFuncAttributeMaxDynamicSharedMemorySize, GEMM_SMEM);
    cudaFuncSetAttribute(gemm_scores, cudaFuncAttributeMaxDynamicSharedMemorySize, GEMM_SMEM);

    // 1) LayerNorm + split
    ln_split_kernel<<<ROWS, 256>>>(h, gamma, beta);

    // 2) Weight transpose + split
    wprep_kernel<<<dim3(24, 24, 2), dim3(32, 8)>>>(wq, wk);

    // 3) Merged Q+K projections
    gemm_proj<<<dim3(12, ROWS / 128), 256, GEMM_SMEM>>>(bq, bk);

    // 4) Scores
    gemm_scores<<<dim3(SEQ / 128, SEQ / 128, BATCH), 256, GEMM_SMEM>>>(out);

    // 5) Softmax in place
    softmax_kernel<<<ROWS, 256>>>(out);
}